// round 2
// baseline (speedup 1.0000x reference)
#include <cuda_runtime.h>
#include <math.h>

#define NTOK 131072      // B*S = 64*2048 tokens
#define KC   128         // memory bank size
#define DD   192         // projection dim
#define TOKT 128         // tokens per block in sim kernel
#define CH   32          // d-chunk staged in smem
#define XPITCH 132       // padded token pitch (16B aligned rows, conflict-spread)

// ---------------- scratch (static __device__: no allocation) ----------------
__device__ float g_E[(size_t)NTOK * KC];        // exp(sim/0.05), [token][k], 64 MiB
__device__ float g_memn_t[DD * KC];             // normalized mem bank, transposed [d][k]
__device__ float g_gated[KC * DD];              // precomputed GLU(mem_bank) table
__device__ float g_a[KC];                       // current row scaling (a1/a2/a3)
__device__ float g_partA[(NTOK / TOKT) * KC];   // 1024 x 128 rowsum partials
__device__ float g_partB[512 * KC];             // sinkhorn pass partials

// ---------------- prep: normalize bank + GLU table --------------------------
__global__ void prep_kernel(const float* __restrict__ mb,
                            const float* __restrict__ gw,
                            const float* __restrict__ gb) {
    __shared__ float row[DD];
    __shared__ float lin[2 * DD];
    __shared__ float invn_sh;
    int k = blockIdx.x, t = threadIdx.x;
    if (t < DD) row[t] = mb[k * DD + t];
    __syncthreads();
    if (t == 0) {
        float ss = 0.f;
        for (int d = 0; d < DD; d++) ss += row[d] * row[d];
        invn_sh = 1.0f / sqrtf(fmaxf(ss, 1e-12f));
    }
    __syncthreads();
    if (t < DD) g_memn_t[t * KC + k] = row[t] * invn_sh;   // transposed store
    // GLU: lin = mem_bank[k] @ glu_w + glu_b  (2D = 384 = blockDim.x)
    float acc = gb[t];
    for (int j = 0; j < DD; j++) acc = fmaf(row[j], gw[j * (2 * DD) + t], acc);
    lin[t] = acc;
    __syncthreads();
    if (t < DD) {
        float gate = lin[t + DD];
        float s = 1.0f / (1.0f + expf(-gate));
        g_gated[k * DD + t] = lin[t] * s;
    }
}

// ---------------- sim GEMM + exp + rowsum partials ---------------------------
// block: 256 threads -> tile [128 codes x 128 tokens], 8x8 register tile/thread
__global__ __launch_bounds__(256, 2)
void simexp_kernel(const float* __restrict__ x) {
    __shared__ float ms[CH * KC];        // memn chunk [dd][k]
    __shared__ float xt[CH * XPITCH];    // x chunk transposed+normalized [dd][tok]
    __shared__ float invn[TOKT];
    __shared__ float sred[KC * 16];

    int tid  = threadIdx.x;
    int lane = tid & 31, w = tid >> 5;
    int tok0 = blockIdx.x * TOKT;

    // phase 0: per-token inverse L2 norm (deterministic warp tree)
    for (int t = w; t < TOKT; t += 8) {
        const float* xp = x + (size_t)(tok0 + t) * DD;
        float ss = 0.f;
        #pragma unroll
        for (int m = 0; m < 6; m++) { float v = xp[lane + 32 * m]; ss = fmaf(v, v, ss); }
        #pragma unroll
        for (int o = 16; o > 0; o >>= 1) ss += __shfl_xor_sync(0xffffffffu, ss, o);
        if (lane == 0) invn[t] = 1.0f / sqrtf(fmaxf(ss, 1e-12f));
    }
    __syncthreads();

    int r = tid >> 4;    // code group  (8 codes each)
    int c = tid & 15;    // token group (8 tokens each)

    float acc[8][8];
    #pragma unroll
    for (int i = 0; i < 8; i++)
        #pragma unroll
        for (int j = 0; j < 8; j++) acc[i][j] = 0.f;

    for (int d0 = 0; d0 < DD; d0 += CH) {
        for (int i = tid; i < CH * KC; i += 256)
            ms[i] = g_memn_t[d0 * KC + i];
        for (int i = tid; i < TOKT * CH; i += 256) {
            int tt = i >> 5;           // i / CH  (CH == 32)
            int dd = i & 31;
            float v = x[(size_t)(tok0 + tt) * DD + d0 + dd];
            xt[dd * XPITCH + tt] = v * invn[tt];
        }
        __syncthreads();
        #pragma unroll 2
        for (int dd = 0; dd < CH; dd++) {
            float4 a0 = *reinterpret_cast<const float4*>(&ms[dd * KC + 8 * r]);
            float4 a1 = *reinterpret_cast<const float4*>(&ms[dd * KC + 8 * r + 4]);
            float4 b0 = *reinterpret_cast<const float4*>(&xt[dd * XPITCH + 8 * c]);
            float4 b1 = *reinterpret_cast<const float4*>(&xt[dd * XPITCH + 8 * c + 4]);
            float av[8] = {a0.x, a0.y, a0.z, a0.w, a1.x, a1.y, a1.z, a1.w};
            float bv[8] = {b0.x, b0.y, b0.z, b0.w, b1.x, b1.y, b1.z, b1.w};
            #pragma unroll
            for (int i = 0; i < 8; i++)
                #pragma unroll
                for (int j = 0; j < 8; j++)
                    acc[i][j] = fmaf(av[i], bv[j], acc[i][j]);
        }
        __syncthreads();
    }

    // epilogue: E = exp(20*sim), store, per-code token sums for rowsum(E)
    float s0[8];
    #pragma unroll
    for (int i = 0; i < 8; i++) s0[i] = 0.f;
    #pragma unroll
    for (int j = 0; j < 8; j++) {
        int n = tok0 + 8 * c + j;
        float e[8];
        #pragma unroll
        for (int i = 0; i < 8; i++) {
            e[i] = expf(acc[i][j] * 20.0f);
            s0[i] += e[i];
        }
        float4* dst = reinterpret_cast<float4*>(&g_E[(size_t)n * KC + 8 * r]);
        dst[0] = make_float4(e[0], e[1], e[2], e[3]);
        dst[1] = make_float4(e[4], e[5], e[6], e[7]);
    }
    #pragma unroll
    for (int i = 0; i < 8; i++) sred[(8 * r + i) * 16 + c] = s0[i];
    __syncthreads();
    if (tid < KC) {
        float s = 0.f;
        #pragma unroll
        for (int cc = 0; cc < 16; cc++) s += sred[tid * 16 + cc];
        g_partA[blockIdx.x * KC + tid] = s;
    }
}

// ---------------- reduce partials -> a = 1/rowsum ----------------------------
__global__ void reduce_part_kernel(int which, int nparts) {
    const float* part = which ? g_partB : g_partA;
    __shared__ float sm[256];
    int k = blockIdx.x, t = threadIdx.x;
    float s = 0.f;
    for (int b = t; b < nparts; b += 256) s += part[b * KC + k];
    sm[t] = s;
    __syncthreads();
    for (int o = 128; o > 0; o >>= 1) {
        if (t < o) sm[t] += sm[t + o];
        __syncthreads();
    }
    if (t == 0) g_a[k] = 1.0f / sm[0];
}

// ---------------- fused Sinkhorn pass: col-normalize then rowsum(E*b) --------
// warp per 32 tokens; colsum_n = sum_k E[n][k]*a_k ; b_n = 1/colsum (consts drop)
__global__ void sinkhorn_pass_kernel() {
    __shared__ float ps[8 * KC];
    int tid = threadIdx.x, lane = tid & 31, w = tid >> 5;
    int g = blockIdx.x * 8 + w;
    float4 av = *reinterpret_cast<const float4*>(&g_a[lane * 4]);
    float r0 = 0.f, r1 = 0.f, r2 = 0.f, r3 = 0.f;
    size_t base = (size_t)g * 32 * KC;
    for (int i = 0; i < 32; i++) {
        float4 e = *reinterpret_cast<const float4*>(&g_E[base + (size_t)i * KC + lane * 4]);
        float s = e.x * av.x + e.y * av.y + e.z * av.z + e.w * av.w;
        #pragma unroll
        for (int o = 16; o > 0; o >>= 1) s += __shfl_xor_sync(0xffffffffu, s, o);
        float b = 1.0f / s;
        r0 = fmaf(e.x, b, r0); r1 = fmaf(e.y, b, r1);
        r2 = fmaf(e.z, b, r2); r3 = fmaf(e.w, b, r3);
    }
    ps[w * KC + lane * 4 + 0] = r0;
    ps[w * KC + lane * 4 + 1] = r1;
    ps[w * KC + lane * 4 + 2] = r2;
    ps[w * KC + lane * 4 + 3] = r3;
    __syncthreads();
    if (tid < KC) {
        float s = 0.f;
        #pragma unroll
        for (int ww = 0; ww < 8; ww++) s += ps[ww * KC + tid];
        g_partB[blockIdx.x * KC + tid] = s;
    }
}

// ---------------- argmax + gather + residual average -------------------------
__global__ void output_kernel(const float* __restrict__ x, float* __restrict__ out) {
    int tid = threadIdx.x, lane = tid & 31, w = tid >> 5;
    int g = blockIdx.x * 8 + w;
    float4 av = *reinterpret_cast<const float4*>(&g_a[lane * 4]);
    for (int i = 0; i < 8; i++) {
        int n = g * 8 + i;
        float4 e = *reinterpret_cast<const float4*>(&g_E[(size_t)n * KC + lane * 4]);
        float v0 = e.x * av.x, v1 = e.y * av.y, v2 = e.z * av.z, v3 = e.w * av.w;
        float best = v0; int bk = lane * 4;
        if (v1 > best) { best = v1; bk = lane * 4 + 1; }
        if (v2 > best) { best = v2; bk = lane * 4 + 2; }
        if (v3 > best) { best = v3; bk = lane * 4 + 3; }
        #pragma unroll
        for (int o = 16; o > 0; o >>= 1) {  // max with min-index tie-break (assoc+comm)
            float ov = __shfl_xor_sync(0xffffffffu, best, o);
            int   ok = __shfl_xor_sync(0xffffffffu, bk, o);
            if (ov > best || (ov == best && ok < bk)) { best = ov; bk = ok; }
        }
        const float* gp = g_gated + (size_t)bk * DD;
        const float* xp = x + (size_t)n * DD;
        float* op = out + (size_t)n * DD;
        #pragma unroll
        for (int m = 0; m < 6; m++) {
            int d = lane + 32 * m;
            op[d] = (xp[d] + gp[d]) * 0.5f;
        }
    }
}

// ---------------- launch ------------------------------------------------------
extern "C" void kernel_launch(void* const* d_in, const int* in_sizes, int n_in,
                              void* d_out, int out_size) {
    const float* proj = (const float*)d_in[0];   // [64,2048,192]
    const float* mb   = (const float*)d_in[1];   // [128,192]
    const float* gw   = (const float*)d_in[2];   // [192,384]
    const float* gb   = (const float*)d_in[3];   // [384]
    float* out = (float*)d_out;

    prep_kernel<<<KC, 2 * DD>>>(mb, gw, gb);
    simexp_kernel<<<NTOK / TOKT, 256>>>(proj);           // E + rowsum partials
    reduce_part_kernel<<<KC, 256>>>(0, NTOK / TOKT);     // a1
    sinkhorn_pass_kernel<<<512, 256>>>();                // b1 -> rowsum partials
    reduce_part_kernel<<<KC, 256>>>(1, 512);             // a2
    sinkhorn_pass_kernel<<<512, 256>>>();                // b2 -> rowsum partials
    reduce_part_kernel<<<KC, 256>>>(1, 512);             // a3
    output_kernel<<<NTOK / 64, 256>>>(proj, out);        // argmax + GLU gather
}

// round 3
// speedup vs baseline: 1.5976x; 1.5976x over previous
#include <cuda_runtime.h>
#include <math.h>

#define NTOK 131072      // B*S = 64*2048 tokens
#define KC   128         // memory bank size
#define DD   192         // projection dim
#define TOKT 128         // tokens per block in sim kernel
#define CH   32          // d-chunk staged in smem
#define XPITCH 132       // padded token pitch (16B aligned rows)
#define SKB  2048        // sinkhorn pass grid

typedef unsigned long long u64;

// ---------------- scratch (static __device__: no allocation) ----------------
__device__ float g_E[(size_t)NTOK * KC];        // exp(sim/0.05), [token][k], 64 MiB
__device__ float g_memn_t[DD * KC];             // normalized mem bank, transposed [d][k]
__device__ float g_gated[KC * DD];              // precomputed GLU(mem_bank) table
__device__ float g_a[KC];                       // current row scaling (a1/a2/a3)
__device__ float g_partA[(NTOK / TOKT) * KC];   // 1024 x 128 rowsum partials
__device__ float g_partB[SKB * KC];             // sinkhorn pass partials

// packed f32x2 helpers (Blackwell-only; ptxas never auto-fuses these)
#define FMA2(acc, a, b) \
    asm("fma.rn.f32x2 %0, %1, %2, %0;" : "+l"(acc) : "l"(a), "l"(b))
#define PACKDUP(dst, v) \
    asm("mov.b64 %0, {%1, %1};" : "=l"(dst) : "f"(v))
#define UNPACK2(lo, hi, p) \
    asm("mov.b64 {%0, %1}, %2;" : "=f"(lo), "=f"(hi) : "l"(p))

// ---------------- prep: normalize bank + GLU table --------------------------
__global__ void prep_kernel(const float* __restrict__ mb,
                            const float* __restrict__ gw,
                            const float* __restrict__ gb) {
    __shared__ float row[DD];
    __shared__ float lin[2 * DD];
    __shared__ float invn_sh;
    int k = blockIdx.x, t = threadIdx.x;
    if (t < DD) row[t] = mb[k * DD + t];
    __syncthreads();
    if (t == 0) {
        float ss = 0.f;
        for (int d = 0; d < DD; d++) ss += row[d] * row[d];
        invn_sh = 1.0f / sqrtf(fmaxf(ss, 1e-12f));
    }
    __syncthreads();
    if (t < DD) g_memn_t[t * KC + k] = row[t] * invn_sh;   // transposed store
    float acc = gb[t];
    for (int j = 0; j < DD; j++) acc = fmaf(row[j], gw[j * (2 * DD) + t], acc);
    lin[t] = acc;
    __syncthreads();
    if (t < DD) {
        float gate = lin[t + DD];
        float s = 1.0f / (1.0f + expf(-gate));
        g_gated[k * DD + t] = lin[t] * s;
    }
}

// ---------------- sim GEMM (f32x2) + exp + rowsum partials -------------------
// block: 256 threads -> tile [128 codes x 128 tokens]
// per thread: 8 codes x 8 tokens, accumulated as 8 x 4 packed f32x2 pairs
__global__ __launch_bounds__(256, 2)
void simexp_kernel(const float* __restrict__ x) {
    __shared__ float ms[CH * KC];        // memn chunk [dd][k]
    __shared__ float xt[CH * XPITCH];    // x chunk transposed (raw) [dd][tok]
    __shared__ float invn[TOKT];
    __shared__ float sred[KC * 16];

    int tid  = threadIdx.x;
    int lane = tid & 31, w = tid >> 5;
    int tok0 = blockIdx.x * TOKT;

    // phase 0: per-token inverse L2 norm (deterministic warp tree)
    for (int t = w; t < TOKT; t += 8) {
        const float* xp = x + (size_t)(tok0 + t) * DD;
        float ss = 0.f;
        #pragma unroll
        for (int m = 0; m < 6; m++) { float v = xp[lane + 32 * m]; ss = fmaf(v, v, ss); }
        #pragma unroll
        for (int o = 16; o > 0; o >>= 1) ss += __shfl_xor_sync(0xffffffffu, ss, o);
        if (lane == 0) invn[t] = 1.0f / sqrtf(fmaxf(ss, 1e-12f));
    }
    __syncthreads();

    int r = tid >> 4;    // code group  (8 codes each)
    int c = tid & 15;    // token group (8 tokens each)

    u64 acc2[8][4];      // [code i][token-pair jp]; 0ull == packed {0.f, 0.f}
    #pragma unroll
    for (int i = 0; i < 8; i++)
        #pragma unroll
        for (int jp = 0; jp < 4; jp++) acc2[i][jp] = 0ull;

    for (int d0 = 0; d0 < DD; d0 += CH) {
        for (int i = tid; i < CH * KC; i += 256)
            ms[i] = g_memn_t[d0 * KC + i];
        for (int i = tid; i < TOKT * CH; i += 256) {
            int tt = i >> 5;           // i / CH  (CH == 32)
            int dd = i & 31;
            xt[dd * XPITCH + tt] = x[(size_t)(tok0 + tt) * DD + d0 + dd];
        }
        __syncthreads();
        #pragma unroll 2
        for (int dd = 0; dd < CH; dd++) {
            float4 a0 = *reinterpret_cast<const float4*>(&ms[dd * KC + 8 * r]);
            float4 a1 = *reinterpret_cast<const float4*>(&ms[dd * KC + 8 * r + 4]);
            u64 a2[8];
            PACKDUP(a2[0], a0.x); PACKDUP(a2[1], a0.y);
            PACKDUP(a2[2], a0.z); PACKDUP(a2[3], a0.w);
            PACKDUP(a2[4], a1.x); PACKDUP(a2[5], a1.y);
            PACKDUP(a2[6], a1.z); PACKDUP(a2[7], a1.w);
            // token pairs already adjacent in smem -> LDS.128 yields packed pairs
            ulonglong2 bb0 = *reinterpret_cast<const ulonglong2*>(&xt[dd * XPITCH + 8 * c]);
            ulonglong2 bb1 = *reinterpret_cast<const ulonglong2*>(&xt[dd * XPITCH + 8 * c + 4]);
            u64 b2[4] = {bb0.x, bb0.y, bb1.x, bb1.y};
            #pragma unroll
            for (int i = 0; i < 8; i++) {
                #pragma unroll
                for (int jp = 0; jp < 4; jp++)
                    FMA2(acc2[i][jp], a2[i], b2[jp]);
            }
        }
        __syncthreads();
    }

    // epilogue: sim = dot * invn_token; E = exp(20*sim); store + rowsum partials
    float s0[8];
    #pragma unroll
    for (int i = 0; i < 8; i++) s0[i] = 0.f;
    #pragma unroll
    for (int jp = 0; jp < 4; jp++) {
        int tLo = 8 * c + 2 * jp, tHi = tLo + 1;
        float sl = 20.0f * invn[tLo];
        float sh = 20.0f * invn[tHi];
        float eL[8], eH[8];
        #pragma unroll
        for (int i = 0; i < 8; i++) {
            float lo, hi;
            UNPACK2(lo, hi, acc2[i][jp]);
            eL[i] = expf(lo * sl);
            eH[i] = expf(hi * sh);
            s0[i] += eL[i] + eH[i];
        }
        float4* dL = reinterpret_cast<float4*>(&g_E[(size_t)(tok0 + tLo) * KC + 8 * r]);
        dL[0] = make_float4(eL[0], eL[1], eL[2], eL[3]);
        dL[1] = make_float4(eL[4], eL[5], eL[6], eL[7]);
        float4* dH = reinterpret_cast<float4*>(&g_E[(size_t)(tok0 + tHi) * KC + 8 * r]);
        dH[0] = make_float4(eH[0], eH[1], eH[2], eH[3]);
        dH[1] = make_float4(eH[4], eH[5], eH[6], eH[7]);
    }
    #pragma unroll
    for (int i = 0; i < 8; i++) sred[(8 * r + i) * 16 + c] = s0[i];
    __syncthreads();
    if (tid < KC) {
        float s = 0.f;
        #pragma unroll
        for (int cc = 0; cc < 16; cc++) s += sred[tid * 16 + cc];
        g_partA[blockIdx.x * KC + tid] = s;
    }
}

// ---------------- reduce partials -> a = 1/rowsum ----------------------------
__global__ void reduce_part_kernel(int which, int nparts) {
    const float* part = which ? g_partB : g_partA;
    __shared__ float sm[256];
    int k = blockIdx.x, t = threadIdx.x;
    float s = 0.f;
    for (int b = t; b < nparts; b += 256) s += part[b * KC + k];
    sm[t] = s;
    __syncthreads();
    for (int o = 128; o > 0; o >>= 1) {
        if (t < o) sm[t] += sm[t + o];
        __syncthreads();
    }
    if (t == 0) g_a[k] = 1.0f / sm[0];
}

// ---------------- fused Sinkhorn pass: col-normalize then rowsum(E*b) --------
// warp per 8 tokens; grid SKB blocks of 8 warps
__global__ void sinkhorn_pass_kernel() {
    __shared__ float ps[8 * KC];
    int tid = threadIdx.x, lane = tid & 31, w = tid >> 5;
    int g = blockIdx.x * 8 + w;
    float4 av = *reinterpret_cast<const float4*>(&g_a[lane * 4]);
    float r0 = 0.f, r1 = 0.f, r2 = 0.f, r3 = 0.f;
    size_t base = (size_t)g * 8 * KC;
    #pragma unroll 2
    for (int i = 0; i < 8; i++) {
        float4 e = *reinterpret_cast<const float4*>(&g_E[base + (size_t)i * KC + lane * 4]);
        float s = e.x * av.x + e.y * av.y + e.z * av.z + e.w * av.w;
        #pragma unroll
        for (int o = 16; o > 0; o >>= 1) s += __shfl_xor_sync(0xffffffffu, s, o);
        float b = 1.0f / s;
        r0 = fmaf(e.x, b, r0); r1 = fmaf(e.y, b, r1);
        r2 = fmaf(e.z, b, r2); r3 = fmaf(e.w, b, r3);
    }
    ps[w * KC + lane * 4 + 0] = r0;
    ps[w * KC + lane * 4 + 1] = r1;
    ps[w * KC + lane * 4 + 2] = r2;
    ps[w * KC + lane * 4 + 3] = r3;
    __syncthreads();
    if (tid < KC) {
        float s = 0.f;
        #pragma unroll
        for (int ww = 0; ww < 8; ww++) s += ps[ww * KC + tid];
        g_partB[blockIdx.x * KC + tid] = s;
    }
}

// ---------------- argmax + gather + residual average -------------------------
__global__ void output_kernel(const float* __restrict__ x, float* __restrict__ out) {
    int tid = threadIdx.x, lane = tid & 31, w = tid >> 5;
    int g = blockIdx.x * 8 + w;
    float4 av = *reinterpret_cast<const float4*>(&g_a[lane * 4]);
    for (int i = 0; i < 8; i++) {
        int n = g * 8 + i;
        float4 e = *reinterpret_cast<const float4*>(&g_E[(size_t)n * KC + lane * 4]);
        float v0 = e.x * av.x, v1 = e.y * av.y, v2 = e.z * av.z, v3 = e.w * av.w;
        float best = v0; int bk = lane * 4;
        if (v1 > best) { best = v1; bk = lane * 4 + 1; }
        if (v2 > best) { best = v2; bk = lane * 4 + 2; }
        if (v3 > best) { best = v3; bk = lane * 4 + 3; }
        #pragma unroll
        for (int o = 16; o > 0; o >>= 1) {  // max with min-index tie-break (assoc+comm)
            float ov = __shfl_xor_sync(0xffffffffu, best, o);
            int   ok = __shfl_xor_sync(0xffffffffu, bk, o);
            if (ov > best || (ov == best && ok < bk)) { best = ov; bk = ok; }
        }
        const float* gp = g_gated + (size_t)bk * DD;
        const float* xp = x + (size_t)n * DD;
        float* op = out + (size_t)n * DD;
        #pragma unroll
        for (int m = 0; m < 6; m++) {
            int d = lane + 32 * m;
            op[d] = (xp[d] + gp[d]) * 0.5f;
        }
    }
}

// ---------------- launch ------------------------------------------------------
extern "C" void kernel_launch(void* const* d_in, const int* in_sizes, int n_in,
                              void* d_out, int out_size) {
    const float* proj = (const float*)d_in[0];   // [64,2048,192]
    const float* mb   = (const float*)d_in[1];   // [128,192]
    const float* gw   = (const float*)d_in[2];   // [192,384]
    const float* gb   = (const float*)d_in[3];   // [384]
    float* out = (float*)d_out;

    prep_kernel<<<KC, 2 * DD>>>(mb, gw, gb);
    simexp_kernel<<<NTOK / TOKT, 256>>>(proj);           // E + rowsum partials
    reduce_part_kernel<<<KC, 256>>>(0, NTOK / TOKT);     // a1
    sinkhorn_pass_kernel<<<SKB, 256>>>();                // b1 -> rowsum partials
    reduce_part_kernel<<<KC, 256>>>(1, SKB);             // a2
    sinkhorn_pass_kernel<<<SKB, 256>>>();                // b2 -> rowsum partials
    reduce_part_kernel<<<KC, 256>>>(1, SKB);             // a3
    output_kernel<<<NTOK / 64, 256>>>(proj, out);        // argmax + GLU gather
}

// round 10
// speedup vs baseline: 1.7913x; 1.1212x over previous
#include <cuda_runtime.h>
#include <math.h>
#include <cstdint>

#define NTOK 131072      // B*S tokens
#define KC   128         // memory bank size
#define DD   192         // projection dim
#define TOKT 128         // tokens per block in sim kernel
#define SKB  2048        // sinkhorn pass grid
#define BPITCH 36        // token-row pitch (floats) in B smem: 4n+k conflict-free

typedef unsigned int u32;

// ---------------- scratch (static __device__: no allocation) ----------------
__device__ float g_E[(size_t)NTOK * KC];        // exp(sim/0.05), [token][k], 64 MiB
__device__ u32   g_afrag_hi[24 * 8 * 32 * 4];   // A frags [kc][mt][t][reg], tf32 hi
__device__ u32   g_afrag_lo[24 * 8 * 32 * 4];   // tf32 lo
__device__ float g_memn[KC * DD];               // normalized codes fp32 (exact path)
__device__ float g_gated[KC * DD];              // precomputed GLU(mem_bank) table
__device__ float g_a[KC];                       // current row scaling
__device__ float g_la[KC];                      // ln(a)
__device__ float g_partA[(NTOK / TOKT) * KC];   // simexp rowsum partials
__device__ float g_partB[SKB * KC];             // sinkhorn pass partials

__device__ __forceinline__ u32 f2tf32(float f) {
    u32 r; asm("cvt.rna.tf32.f32 %0, %1;" : "=r"(r) : "f"(f)); return r;
}
__device__ __forceinline__ void mma_tf32(float* d, const u32* a, u32 b0, u32 b1) {
    asm volatile(
        "mma.sync.aligned.m16n8k8.row.col.f32.tf32.tf32.f32 "
        "{%0,%1,%2,%3}, {%4,%5,%6,%7}, {%8,%9}, {%0,%1,%2,%3};"
        : "+f"(d[0]), "+f"(d[1]), "+f"(d[2]), "+f"(d[3])
        : "r"(a[0]), "r"(a[1]), "r"(a[2]), "r"(a[3]), "r"(b0), "r"(b1));
}

// ---------------- prep: normalize bank, A frags (tf32), GLU table ------------
__global__ void prep_kernel(const float* __restrict__ mb,
                            const float* __restrict__ gw,
                            const float* __restrict__ gb) {
    __shared__ float row[DD];
    __shared__ float lin[2 * DD];
    __shared__ float invn_sh;
    int m = blockIdx.x, t = threadIdx.x;
    if (t < DD) row[t] = mb[m * DD + t];
    __syncthreads();
    if (t == 0) {
        float ss = 0.f;
        for (int d = 0; d < DD; d++) ss += row[d] * row[d];
        invn_sh = 1.0f / sqrtf(fmaxf(ss, 1e-12f));
    }
    __syncthreads();
    if (t < DD) {
        float v = row[t] * invn_sh;
        g_memn[m * DD + t] = v;
        // fragment coords for mma.m16n8k8 tf32 A (row-major):
        int kc = t >> 3, kk = t & 7;
        int mt = m >> 4, rin = m & 15;
        int reg = ((rin >> 3) & 1) | ((kk >> 2) << 1);
        int tt  = (rin & 7) * 4 + (kk & 3);
        int idx = ((kc * 8 + mt) * 32 + tt) * 4 + reg;
        u32 hi = f2tf32(v);
        float lo = v - __uint_as_float(hi);
        g_afrag_hi[idx] = hi;
        g_afrag_lo[idx] = f2tf32(lo);
    }
    float acc = gb[t];
    for (int j = 0; j < DD; j++) acc = fmaf(row[j], gw[j * (2 * DD) + t], acc);
    lin[t] = acc;
    __syncthreads();
    if (t < DD) {
        float gate = lin[t + DD];
        float s = 1.0f / (1.0f + expf(-gate));
        g_gated[m * DD + t] = lin[t] * s;
    }
}

// ---------------- sim GEMM via mma.sync tf32 3-pass + expf + rowsum ----------
// CTA 256 thr / 8 warps: tile 128 codes x 128 tokens, K=192 in 6 chunks of 32.
// warp w: codes [32*(w/2), +32), tokens [64*(w%2), +64).
__global__ __launch_bounds__(256, 2)
void simexp_mma_kernel(const float* __restrict__ x) {
    extern __shared__ char dyn[];
    u32*   afh   = (u32*)(dyn);
    u32*   afl   = (u32*)(dyn + 16384);
    u32*   xhi   = (u32*)(dyn + 32768);
    u32*   xlo   = (u32*)(dyn + 51200);
    float* sq    = (float*)(dyn + 69632);
    float* invn  = (float*)(dyn + 70656);
    float* ps    = (float*)(dyn + 71168);   // [8][32]

    int tid = threadIdx.x, lane = tid & 31, w = tid >> 5;
    int mt2 = w >> 1;          // code block (32 codes)
    int nt8 = w & 1;           // token half (64 tokens)
    int tok0 = blockIdx.x * TOKT;

    int tk = tid >> 1, h = tid & 1;          // staging: token, half(16 floats)
    float ss = 0.f;

    float acc[2][8][4];
    #pragma unroll
    for (int mi = 0; mi < 2; mi++)
        #pragma unroll
        for (int nt = 0; nt < 8; nt++)
            #pragma unroll
            for (int r = 0; r < 4; r++) acc[mi][nt][r] = 0.f;

    for (int c = 0; c < 6; c++) {
        // stage A frags (straight copy, frag-ordered in prep)
        {
            const uint4* src_h = (const uint4*)(g_afrag_hi + c * 4096);
            const uint4* src_l = (const uint4*)(g_afrag_lo + c * 4096);
            uint4* dh = (uint4*)afh; uint4* dl = (uint4*)afl;
            #pragma unroll
            for (int i = 0; i < 4; i++) {
                dh[tid + 256 * i] = src_h[tid + 256 * i];
                dl[tid + 256 * i] = src_l[tid + 256 * i];
            }
        }
        // stage B: 16 contiguous floats of token tk, tf32 split + sumsq
        {
            const float4* src = (const float4*)(x + (size_t)(tok0 + tk) * DD + c * 32 + h * 16);
            u32* bh = xhi + tk * BPITCH + h * 16;
            u32* bl = xlo + tk * BPITCH + h * 16;
            #pragma unroll
            for (int q = 0; q < 4; q++) {
                float4 v4 = src[q];
                float vv[4] = {v4.x, v4.y, v4.z, v4.w};
                #pragma unroll
                for (int j = 0; j < 4; j++) {
                    float v = vv[j];
                    ss = fmaf(v, v, ss);
                    u32 hi = f2tf32(v);
                    bh[q * 4 + j] = hi;
                    bl[q * 4 + j] = f2tf32(v - __uint_as_float(hi));
                }
            }
        }
        __syncthreads();

        #pragma unroll
        for (int ks = 0; ks < 4; ks++) {
            u32 ah[2][4], al[2][4];
            #pragma unroll
            for (int mi = 0; mi < 2; mi++) {
                int mt = mt2 * 2 + mi;
                const uint4* ph = (const uint4*)(afh + ((ks * 8 + mt) * 32 + lane) * 4);
                const uint4* pl = (const uint4*)(afl + ((ks * 8 + mt) * 32 + lane) * 4);
                uint4 th = *ph; ah[mi][0] = th.x; ah[mi][1] = th.y; ah[mi][2] = th.z; ah[mi][3] = th.w;
                uint4 tl = *pl; al[mi][0] = tl.x; al[mi][1] = tl.y; al[mi][2] = tl.z; al[mi][3] = tl.w;
            }
            #pragma unroll
            for (int nt = 0; nt < 8; nt++) {
                int nrow = nt8 * 64 + nt * 8 + (lane >> 2);
                int kcol = ks * 8 + (lane & 3);
                u32 bh0 = xhi[nrow * BPITCH + kcol];
                u32 bh1 = xhi[nrow * BPITCH + kcol + 4];
                u32 bl0 = xlo[nrow * BPITCH + kcol];
                u32 bl1 = xlo[nrow * BPITCH + kcol + 4];
                #pragma unroll
                for (int mi = 0; mi < 2; mi++) {
                    mma_tf32(acc[mi][nt], ah[mi], bh0, bh1);   // hi*hi
                    mma_tf32(acc[mi][nt], ah[mi], bl0, bl1);   // hi*lo
                    mma_tf32(acc[mi][nt], al[mi], bh0, bh1);   // lo*hi
                }
            }
        }
        __syncthreads();
    }

    // finalize per-token inv norms
    sq[tid] = ss;
    __syncthreads();
    if (tid < TOKT)
        invn[tid] = 1.0f / sqrtf(fmaxf(sq[2 * tid] + sq[2 * tid + 1], 1e-12f));
    __syncthreads();

    // epilogue: E = expf(20*sim*invn), store + rowsum partials
    float racc[4] = {0.f, 0.f, 0.f, 0.f};   // [mi*2 + rowhalf]
    #pragma unroll
    for (int mi = 0; mi < 2; mi++)
        #pragma unroll
        for (int nt = 0; nt < 8; nt++)
            #pragma unroll
            for (int r = 0; r < 4; r++) {
                int code = mt2 * 32 + mi * 16 + (lane >> 2) + ((r >> 1) << 3);
                int n = nt8 * 64 + nt * 8 + (lane & 3) * 2 + (r & 1);
                float e = expf(acc[mi][nt][r] * (20.0f * invn[n]));
                g_E[(size_t)(tok0 + n) * KC + code] = e;
                racc[mi * 2 + (r >> 1)] += e;
            }
    #pragma unroll
    for (int q = 0; q < 4; q++) {
        racc[q] += __shfl_xor_sync(0xffffffffu, racc[q], 1);
        racc[q] += __shfl_xor_sync(0xffffffffu, racc[q], 2);
    }
    if ((lane & 3) == 0) {
        #pragma unroll
        for (int q = 0; q < 4; q++) {
            // q = mi*2 + rh  ->  local code = mi*16 + rh*8 + row  (FIXED mapping)
            int cl = (q >> 1) * 16 + (q & 1) * 8 + (lane >> 2);
            ps[w * 32 + cl] = racc[q];
        }
    }
    __syncthreads();
    if (tid < KC) {
        int q = tid >> 5;
        float s = ps[(2 * q) * 32 + (tid & 31)] + ps[(2 * q + 1) * 32 + (tid & 31)];
        g_partA[blockIdx.x * KC + tid] = s;
    }
}

// ---------------- reduce partials -> a = 1/rowsum, la = ln a -----------------
__global__ void reduce_part_kernel(int which, int nparts) {
    const float* part = which ? g_partB : g_partA;
    __shared__ float sm[256];
    int k = blockIdx.x, t = threadIdx.x;
    float s = 0.f;
    for (int b = t; b < nparts; b += 256) s += part[b * KC + k];
    sm[t] = s;
    __syncthreads();
    for (int o = 128; o > 0; o >>= 1) {
        if (t < o) sm[t] += sm[t + o];
        __syncthreads();
    }
    if (t == 0) { g_a[k] = 1.0f / sm[0]; g_la[k] = -logf(sm[0]); }
}

// ---------------- fused Sinkhorn pass ----------------------------------------
__global__ void sinkhorn_pass_kernel() {
    __shared__ float ps[8 * KC];
    int tid = threadIdx.x, lane = tid & 31, w = tid >> 5;
    int g = blockIdx.x * 8 + w;
    float4 av = *reinterpret_cast<const float4*>(&g_a[lane * 4]);
    size_t base = (size_t)g * 8 * KC;
    float4 e[8];
    #pragma unroll
    for (int i = 0; i < 8; i++)
        e[i] = *reinterpret_cast<const float4*>(&g_E[base + (size_t)i * KC + lane * 4]);
    float r0 = 0.f, r1 = 0.f, r2 = 0.f, r3 = 0.f;
    #pragma unroll
    for (int i = 0; i < 8; i++) {
        float s = e[i].x * av.x + e[i].y * av.y + e[i].z * av.z + e[i].w * av.w;
        #pragma unroll
        for (int o = 16; o > 0; o >>= 1) s += __shfl_xor_sync(0xffffffffu, s, o);
        float b = 1.0f / s;
        r0 = fmaf(e[i].x, b, r0); r1 = fmaf(e[i].y, b, r1);
        r2 = fmaf(e[i].z, b, r2); r3 = fmaf(e[i].w, b, r3);
    }
    ps[w * KC + lane * 4 + 0] = r0;
    ps[w * KC + lane * 4 + 1] = r1;
    ps[w * KC + lane * 4 + 2] = r2;
    ps[w * KC + lane * 4 + 3] = r3;
    __syncthreads();
    if (tid < KC) {
        float s = 0.f;
        #pragma unroll
        for (int ww = 0; ww < 8; ww++) s += ps[ww * KC + tid];
        g_partB[blockIdx.x * KC + tid] = s;
    }
}

// ---------------- argmax (top-2 guarded) + gather + residual avg -------------
__global__ void output_kernel(const float* __restrict__ x, float* __restrict__ out) {
    int tid = threadIdx.x, lane = tid & 31, w = tid >> 5;
    int g = blockIdx.x * 8 + w;
    float4 av = *reinterpret_cast<const float4*>(&g_a[lane * 4]);
    float4 e[8];
    #pragma unroll
    for (int i = 0; i < 8; i++)
        e[i] = *reinterpret_cast<const float4*>(&g_E[(size_t)(g * 8 + i) * KC + lane * 4]);
    for (int i = 0; i < 8; i++) {
        int n = g * 8 + i;
        float v[4] = {e[i].x * av.x, e[i].y * av.y, e[i].z * av.z, e[i].w * av.w};
        float b1 = v[0]; int k1 = lane * 4; float b2 = -1.f;
        #pragma unroll
        for (int j = 1; j < 4; j++) {
            int kk = lane * 4 + j;
            if (v[j] > b1 || (v[j] == b1 && kk < k1)) { b2 = b1; b1 = v[j]; k1 = kk; }
            else b2 = fmaxf(b2, v[j]);
        }
        #pragma unroll
        for (int o = 16; o > 0; o >>= 1) {
            float ov1 = __shfl_xor_sync(0xffffffffu, b1, o);
            int   ok1 = __shfl_xor_sync(0xffffffffu, k1, o);
            float ov2 = __shfl_xor_sync(0xffffffffu, b2, o);
            if (ov1 > b1 || (ov1 == b1 && ok1 < k1)) {
                b2 = fmaxf(b1, ov2); b1 = ov1; k1 = ok1;
            } else {
                if (!(ov1 == b1 && ok1 == k1)) b2 = fmaxf(b2, ov1);
                b2 = fmaxf(b2, ov2);
            }
        }
        int bk = k1;
        // near-tie -> exact fp32 recompute (rare)
        if (b2 >= b1 * 0.9999f) {
            const float* xp = x + (size_t)n * DD;
            float dot[4] = {0.f, 0.f, 0.f, 0.f};
            float ssq = 0.f;
            for (int d = 0; d < DD; d++) {
                float xv = xp[d];
                ssq = fmaf(xv, xv, ssq);
                #pragma unroll
                for (int j = 0; j < 4; j++)
                    dot[j] = fmaf(xv, g_memn[(lane * 4 + j) * DD + d], dot[j]);
            }
            float inv = 1.0f / sqrtf(fmaxf(ssq, 1e-12f));
            float sb = -1e30f; int sk = 0;
            #pragma unroll
            for (int j = 0; j < 4; j++) {
                float sc = 20.0f * dot[j] * inv + g_la[lane * 4 + j];
                int kk = lane * 4 + j;
                if (sc > sb || (sc == sb && kk < sk)) { sb = sc; sk = kk; }
            }
            #pragma unroll
            for (int o = 16; o > 0; o >>= 1) {
                float ov = __shfl_xor_sync(0xffffffffu, sb, o);
                int   ok = __shfl_xor_sync(0xffffffffu, sk, o);
                if (ov > sb || (ov == sb && ok < sk)) { sb = ov; sk = ok; }
            }
            bk = sk;
        }
        const float* gp = g_gated + (size_t)bk * DD;
        const float* xp = x + (size_t)n * DD;
        float* op = out + (size_t)n * DD;
        #pragma unroll
        for (int m = 0; m < 6; m++) {
            int d = lane + 32 * m;
            op[d] = (xp[d] + gp[d]) * 0.5f;
        }
    }
}

// ---------------- launch ------------------------------------------------------
extern "C" void kernel_launch(void* const* d_in, const int* in_sizes, int n_in,
                              void* d_out, int out_size) {
    const float* proj = (const float*)d_in[0];   // [64,2048,192]
    const float* mb   = (const float*)d_in[1];   // [128,192]
    const float* gw   = (const float*)d_in[2];   // [192,384]
    const float* gb   = (const float*)d_in[3];   // [384]
    float* out = (float*)d_out;

    const int SMEM_DYN = 73728;
    cudaFuncSetAttribute(simexp_mma_kernel,
                         cudaFuncAttributeMaxDynamicSharedMemorySize, SMEM_DYN);

    prep_kernel<<<KC, 2 * DD>>>(mb, gw, gb);
    simexp_mma_kernel<<<NTOK / TOKT, 256, SMEM_DYN>>>(proj);  // E + rowsum partials
    reduce_part_kernel<<<KC, 256>>>(0, NTOK / TOKT);          // a1
    sinkhorn_pass_kernel<<<SKB, 256>>>();                     // b1 -> partials
    reduce_part_kernel<<<KC, 256>>>(1, SKB);                  // a2
    sinkhorn_pass_kernel<<<SKB, 256>>>();                     // b2 -> partials
    reduce_part_kernel<<<KC, 256>>>(1, SKB);                  // a3
    output_kernel<<<NTOK / 64, 256>>>(proj, out);             // argmax + GLU gather
}